// round 3
// baseline (speedup 1.0000x reference)
#include <cuda_runtime.h>
#include <cuda_bf16.h>
#include <cstdint>

// ============================================================================
// GGRUCell on GB300 — mma.sync (HMMA) bf16 hi/lo-split GEMMs.
// R3: warp tile 64x64 (CTA 128x256), term-major MMA ordering for ILP.
//
//   R   = sigmoid(prev @ Wr + inp[:,2H:]) * inp[:,:H]
//   out = mask * (tanh(R @ U + inp[:,:H]) + 1) + prev   (update gate cancels)
// fp32 GEMM == Ah@Bh + Ah@Bl + Al@Bh with bf16 planes (rel_err ~2e-6).
// ============================================================================

#define HDIM   1024
#define BATCH  16384

static constexpr int M_TILE = 128;
static constexpr int N_TILE = 256;
static constexpr int KT     = 32;            // K-chunk (elems)
static constexpr int NC     = HDIM / KT;     // 32 chunks
static constexpr int SA     = 40;            // padded smem row stride (bf16)

static constexpr int A_PLANE = 128 * SA * 2;            // 10240 B
static constexpr int B_PLANE = 256 * SA * 2;            // 20480 B
static constexpr int OFF_AH = 0;
static constexpr int OFF_AL = A_PLANE;
static constexpr int OFF_BH = 2 * A_PLANE;
static constexpr int OFF_BL = 2 * A_PLANE + B_PLANE;
static constexpr int STG_BYTES = 2 * A_PLANE + 2 * B_PLANE;   // 61440
static constexpr int SMEM_BYTES = 2 * STG_BYTES;              // 122880

// --------------------------------------------------------------------------
__device__ __forceinline__ uint32_t smem_to_u32(const void* p) {
    uint32_t a;
    asm("{ .reg .u64 t; cvta.to.shared.u64 t, %1; cvt.u32.u64 %0, t; }" : "=r"(a) : "l"(p));
    return a;
}
#define CP_ASYNC16(s, g) \
    asm volatile("cp.async.cg.shared.global [%0], [%1], 16;" :: "r"(s), "l"(g) : "memory")
#define CP_COMMIT() asm volatile("cp.async.commit_group;" ::: "memory")
#define CP_WAIT1()  asm volatile("cp.async.wait_group 1;" ::: "memory")
#define CP_WAIT0()  asm volatile("cp.async.wait_group 0;" ::: "memory")

#define LDSM_X4(r0, r1, r2, r3, addr) \
    asm volatile("ldmatrix.sync.aligned.m8n8.x4.shared.b16 {%0,%1,%2,%3}, [%4];" \
                 : "=r"(r0), "=r"(r1), "=r"(r2), "=r"(r3) : "r"(addr))

#define MMA_BF16(d, a, b) \
    asm volatile("mma.sync.aligned.m16n8k16.row.col.f32.bf16.bf16.f32 " \
                 "{%0,%1,%2,%3}, {%4,%5,%6,%7}, {%8,%9}, {%0,%1,%2,%3};" \
                 : "+f"((d)[0]), "+f"((d)[1]), "+f"((d)[2]), "+f"((d)[3]) \
                 : "r"((a)[0]), "r"((a)[1]), "r"((a)[2]), "r"((a)[3]), \
                   "r"((b)[0]), "r"((b)[1]))

// --------------------------------------------------------------------------
// Scratch (no cudaMalloc allowed)
// --------------------------------------------------------------------------
__device__ __nv_bfloat16 g_W1h[HDIM * HDIM];          // Wr^T hi  [n][k]
__device__ __nv_bfloat16 g_W1l[HDIM * HDIM];
__device__ __nv_bfloat16 g_W2h[HDIM * HDIM];          // U^T hi
__device__ __nv_bfloat16 g_W2l[HDIM * HDIM];
__device__ __nv_bfloat16 g_Ph[(size_t)BATCH * HDIM];  // prev hi
__device__ __nv_bfloat16 g_Pl[(size_t)BATCH * HDIM];
__device__ __nv_bfloat16 g_Rh[(size_t)BATCH * HDIM];  // R = reset*state hi
__device__ __nv_bfloat16 g_Rl[(size_t)BATCH * HDIM];

__device__ __forceinline__ uint32_t pack_bf16(__nv_bfloat16 a, __nv_bfloat16 b) {
    __nv_bfloat162 t; t.x = a; t.y = b;
    return *reinterpret_cast<uint32_t*>(&t);
}
__device__ __forceinline__ void split2(float x, float y, uint32_t& hp, uint32_t& lp) {
    __nv_bfloat16 hx = __float2bfloat16(x), hy = __float2bfloat16(y);
    __nv_bfloat16 lx = __float2bfloat16(x - __bfloat162float(hx));
    __nv_bfloat16 ly = __float2bfloat16(y - __bfloat162float(hy));
    hp = pack_bf16(hx, hy);
    lp = pack_bf16(lx, ly);
}

// --------------------------------------------------------------------------
__global__ void wtrans_kernel(const float* __restrict__ W, int ld, int off, int which) {
    __shared__ float tile[32][33];
    __nv_bfloat16* Oh = which ? g_W2h : g_W1h;
    __nv_bfloat16* Ol = which ? g_W2l : g_W1l;
    int tx = threadIdx.x, ty = threadIdx.y;
    int x0 = blockIdx.x * 32, y0 = blockIdx.y * 32;
#pragma unroll
    for (int j = 0; j < 32; j += 8)
        tile[ty + j][tx] = W[(y0 + ty + j) * ld + off + x0 + tx];
    __syncthreads();
#pragma unroll
    for (int j = 0; j < 32; j += 8) {
        float v = tile[tx][ty + j];
        int o = (x0 + ty + j) * HDIM + (y0 + tx);
        __nv_bfloat16 h = __float2bfloat16(v);
        Oh[o] = h;
        Ol[o] = __float2bfloat16(v - __bfloat162float(h));
    }
}

__global__ void psplit_kernel(const float* __restrict__ prev) {
    size_t i = ((size_t)blockIdx.x * 256 + threadIdx.x) * 4;
    float4 v = *reinterpret_cast<const float4*>(&prev[i]);
    uint32_t h01, l01, h23, l23;
    split2(v.x, v.y, h01, l01);
    split2(v.z, v.w, h23, l23);
    *reinterpret_cast<uint2*>(&g_Ph[i]) = make_uint2(h01, h23);
    *reinterpret_cast<uint2*>(&g_Pl[i]) = make_uint2(l01, l23);
}

// --------------------------------------------------------------------------
// GEMM: CTA 128x256, 8 warps (2M x 4N), warp tile 64x64, K-chunk 32,
// 2-stage cp.async, term-major MMA ordering (accumulator chain distance 8).
// --------------------------------------------------------------------------
template <bool FIRST>
__global__ void __launch_bounds__(256, 1)
gemm_kernel(const float* __restrict__ inp, const float* __restrict__ prev,
            const float* __restrict__ mask, float* __restrict__ out) {
    extern __shared__ char smem_raw[];
    const uint32_t sb = smem_to_u32(smem_raw);

    const int tid   = threadIdx.x;
    const int wid   = tid >> 5;
    const int lane  = tid & 31;
    const int warpM = wid & 1;        // 2 warps over M (64 rows)
    const int warpN = wid >> 1;       // 4 warps over N (64 cols)
    const int m0 = blockIdx.x * M_TILE;
    const int n0 = blockIdx.y * N_TILE;

    const __nv_bfloat16* AHg = FIRST ? g_Ph  : g_Rh;
    const __nv_bfloat16* ALg = FIRST ? g_Pl  : g_Rl;
    const __nv_bfloat16* BHg = FIRST ? g_W1h : g_W2h;
    const __nv_bfloat16* BLg = FIRST ? g_W1l : g_W2l;

    auto issue_chunk = [&](int kc, int stage) {
        const uint32_t s0 = sb + stage * STG_BYTES;
        // A planes: 128 rows x 4 granules (16B) each; 512 granules, 2/thread
#pragma unroll
        for (int i = 0; i < 2; i++) {
            const int g   = tid + i * 256;
            const int row = g >> 2;
            const int ce  = (g & 3) * 8;
            const size_t gA = (size_t)(m0 + row) * HDIM + kc * KT + ce;
            const uint32_t so = (uint32_t)(row * SA + ce) * 2;
            CP_ASYNC16(s0 + OFF_AH + so, AHg + gA);
            CP_ASYNC16(s0 + OFF_AL + so, ALg + gA);
        }
        // B planes: 256 rows x 4 granules; 1024 granules, 4/thread
#pragma unroll
        for (int i = 0; i < 4; i++) {
            const int g   = tid + i * 256;
            const int row = g >> 2;
            const int ce  = (g & 3) * 8;
            const size_t gB = (size_t)(n0 + row) * HDIM + kc * KT + ce;
            const uint32_t so = (uint32_t)(row * SA + ce) * 2;
            CP_ASYNC16(s0 + OFF_BH + so, BHg + gB);
            CP_ASYNC16(s0 + OFF_BL + so, BLg + gB);
        }
    };

    float acc[4][8][4];
#pragma unroll
    for (int i = 0; i < 4; i++)
#pragma unroll
        for (int j = 0; j < 8; j++)
#pragma unroll
            for (int k = 0; k < 4; k++) acc[i][j][k] = 0.f;

    issue_chunk(0, 0); CP_COMMIT();

    for (int c = 0; c < NC; c++) {
        if (c + 1 < NC) {
            issue_chunk(c + 1, (c + 1) & 1);
            CP_COMMIT();
            CP_WAIT1();
        } else {
            CP_WAIT0();
        }
        __syncthreads();

        const uint32_t s0  = sb + (c & 1) * STG_BYTES;
        const uint32_t sAh = s0 + OFF_AH, sAl = s0 + OFF_AL;
        const uint32_t sBh = s0 + OFF_BH, sBl = s0 + OFF_BL;

#pragma unroll
        for (int kb = 0; kb < KT; kb += 16) {
            // ---- B fragments: 8 n-subtiles per plane (4 LDSM.x4 each)
            uint32_t bh[16], bl[16];
            const int q = lane >> 3;                 // 0..3
#pragma unroll
            for (int p = 0; p < 4; p++) {
                const int nrow = warpN * 64 + (p * 2 + (q >> 1)) * 8 + (lane & 7);
                const int kcol = kb + (q & 1) * 8;
                const uint32_t off = (uint32_t)(nrow * SA + kcol) * 2;
                LDSM_X4(bh[4 * p], bh[4 * p + 1], bh[4 * p + 2], bh[4 * p + 3], sBh + off);
                LDSM_X4(bl[4 * p], bl[4 * p + 1], bl[4 * p + 2], bl[4 * p + 3], sBl + off);
            }
            // ---- A fragments + term-major MMAs (chain distance 8)
#pragma unroll
            for (int mi = 0; mi < 4; mi++) {
                const int arow = warpM * 64 + mi * 16 + (lane & 15);
                const int kcol = kb + ((lane >> 4) << 3);
                const uint32_t off = (uint32_t)(arow * SA + kcol) * 2;
                uint32_t ah[4], al[4];
                LDSM_X4(ah[0], ah[1], ah[2], ah[3], sAh + off);
                LDSM_X4(al[0], al[1], al[2], al[3], sAl + off);
#pragma unroll
                for (int ni = 0; ni < 8; ni++) MMA_BF16(acc[mi][ni], ah, &bh[2 * ni]);
#pragma unroll
                for (int ni = 0; ni < 8; ni++) MMA_BF16(acc[mi][ni], ah, &bl[2 * ni]);
#pragma unroll
                for (int ni = 0; ni < 8; ni++) MMA_BF16(acc[mi][ni], al, &bh[2 * ni]);
            }
        }
        __syncthreads();
    }

    // ---- epilogue ----
#pragma unroll
    for (int mi = 0; mi < 4; mi++) {
#pragma unroll
        for (int h = 0; h < 2; h++) {
            const int b = m0 + warpM * 64 + mi * 16 + h * 8 + (lane >> 2);
            float mval = 0.f;
            if (!FIRST) mval = __ldg(&mask[b]);
#pragma unroll
            for (int ni = 0; ni < 8; ni++) {
                const int n = n0 + warpN * 64 + ni * 8 + (lane & 3) * 2;
                const float v0 = acc[mi][ni][2 * h];
                const float v1 = acc[mi][ni][2 * h + 1];
                const float2 si = *reinterpret_cast<const float2*>(
                    &inp[(size_t)b * (3 * HDIM) + n]);
                if (FIRST) {
                    const float2 gi = *reinterpret_cast<const float2*>(
                        &inp[(size_t)b * (3 * HDIM) + 2 * HDIM + n]);
                    const float r0 = si.x / (1.f + __expf(-(v0 + gi.x)));
                    const float r1 = si.y / (1.f + __expf(-(v1 + gi.y)));
                    uint32_t hp, lp;
                    split2(r0, r1, hp, lp);
                    const size_t g = (size_t)b * HDIM + n;
                    *reinterpret_cast<uint32_t*>(&g_Rh[g]) = hp;
                    *reinterpret_cast<uint32_t*>(&g_Rl[g]) = lp;
                } else {
                    const float2 pv = *reinterpret_cast<const float2*>(
                        &prev[(size_t)b * HDIM + n]);
                    float2 o;
                    o.x = mval * (tanhf(v0 + si.x) + 1.f) + pv.x;
                    o.y = mval * (tanhf(v1 + si.y) + 1.f) + pv.y;
                    *reinterpret_cast<float2*>(&out[(size_t)b * HDIM + n]) = o;
                }
            }
        }
    }
}

// --------------------------------------------------------------------------
extern "C" void kernel_launch(void* const* d_in, const int* in_sizes, int n_in,
                              void* d_out, int out_size) {
    const float* inp  = (const float*)d_in[0];   // (B, 3H)
    const float* prev = (const float*)d_in[1];   // (B, H)
    const float* mask = (const float*)d_in[2];   // (B,)
    const float* Wur  = (const float*)d_in[3];   // (H, 2H)
    const float* U    = (const float*)d_in[4];   // (H, H)
    float* out = (float*)d_out;

    cudaFuncSetAttribute(gemm_kernel<true>,
                         cudaFuncAttributeMaxDynamicSharedMemorySize, SMEM_BYTES);
    cudaFuncSetAttribute(gemm_kernel<false>,
                         cudaFuncAttributeMaxDynamicSharedMemorySize, SMEM_BYTES);

    dim3 tb(32, 8), tg(HDIM / 32, HDIM / 32);
    wtrans_kernel<<<tg, tb>>>(Wur, 2 * HDIM, HDIM, 0);   // Wr = Wur[:, H:2H]
    wtrans_kernel<<<tg, tb>>>(U, HDIM, 0, 1);
    psplit_kernel<<<(BATCH * HDIM) / (256 * 4), 256>>>(prev);

    dim3 grid(BATCH / M_TILE, HDIM / N_TILE);
    gemm_kernel<true><<<grid, 256, SMEM_BYTES>>>(inp, prev, mask, out);
    gemm_kernel<false><<<grid, 256, SMEM_BYTES>>>(inp, prev, mask, out);
}

// round 4
// speedup vs baseline: 1.3294x; 1.3294x over previous
#include <cuda_runtime.h>
#include <cuda_bf16.h>
#include <cstdint>

// ============================================================================
// GGRUCell on GB300 — mma.sync (HMMA) bf16 hi/lo-split GEMMs.
// R4: R2 shape (CTA 128x128, warp 64x32, 2 CTAs/SM) + paired-mi term-major
// MMA ordering (accumulator reuse distance 8, not 1).
//
//   R   = sigmoid(prev @ Wr + inp[:,2H:]) * inp[:,:H]
//   out = mask * (tanh(R @ U + inp[:,:H]) + 1) + prev   (update gate cancels)
// fp32 GEMM == Ah@Bh + Ah@Bl + Al@Bh with bf16 planes (rel_err ~2e-6).
// ============================================================================

#define HDIM   1024
#define BATCH  16384

static constexpr int M_TILE = 128;
static constexpr int N_TILE = 128;
static constexpr int KT     = 32;            // K-chunk
static constexpr int NC     = HDIM / KT;     // 32 chunks
static constexpr int SA     = 40;            // padded smem row stride (bf16)

static constexpr int PLANE_BYTES = 128 * SA * 2;        // 10240
static constexpr int OFF_AH = 0;
static constexpr int OFF_AL = PLANE_BYTES;
static constexpr int OFF_BH = 2 * PLANE_BYTES;
static constexpr int OFF_BL = 3 * PLANE_BYTES;
static constexpr int STG_BYTES = 4 * PLANE_BYTES;       // 40960
static constexpr int SMEM_BYTES = 2 * STG_BYTES;        // 81920

// --------------------------------------------------------------------------
__device__ __forceinline__ uint32_t smem_to_u32(const void* p) {
    uint32_t a;
    asm("{ .reg .u64 t; cvta.to.shared.u64 t, %1; cvt.u32.u64 %0, t; }" : "=r"(a) : "l"(p));
    return a;
}
#define CP_ASYNC16(s, g) \
    asm volatile("cp.async.cg.shared.global [%0], [%1], 16;" :: "r"(s), "l"(g) : "memory")
#define CP_COMMIT() asm volatile("cp.async.commit_group;" ::: "memory")
#define CP_WAIT1()  asm volatile("cp.async.wait_group 1;" ::: "memory")
#define CP_WAIT0()  asm volatile("cp.async.wait_group 0;" ::: "memory")

#define LDSM_X4(r0, r1, r2, r3, addr) \
    asm volatile("ldmatrix.sync.aligned.m8n8.x4.shared.b16 {%0,%1,%2,%3}, [%4];" \
                 : "=r"(r0), "=r"(r1), "=r"(r2), "=r"(r3) : "r"(addr))

#define MMA_BF16(d, a, b) \
    asm volatile("mma.sync.aligned.m16n8k16.row.col.f32.bf16.bf16.f32 " \
                 "{%0,%1,%2,%3}, {%4,%5,%6,%7}, {%8,%9}, {%0,%1,%2,%3};" \
                 : "+f"((d)[0]), "+f"((d)[1]), "+f"((d)[2]), "+f"((d)[3]) \
                 : "r"((a)[0]), "r"((a)[1]), "r"((a)[2]), "r"((a)[3]), \
                   "r"((b)[0]), "r"((b)[1]))

// --------------------------------------------------------------------------
// Scratch (no cudaMalloc allowed)
// --------------------------------------------------------------------------
__device__ __nv_bfloat16 g_W1h[HDIM * HDIM];          // Wr^T hi  [n][k]
__device__ __nv_bfloat16 g_W1l[HDIM * HDIM];
__device__ __nv_bfloat16 g_W2h[HDIM * HDIM];          // U^T hi
__device__ __nv_bfloat16 g_W2l[HDIM * HDIM];
__device__ __nv_bfloat16 g_Ph[(size_t)BATCH * HDIM];  // prev hi
__device__ __nv_bfloat16 g_Pl[(size_t)BATCH * HDIM];
__device__ __nv_bfloat16 g_Rh[(size_t)BATCH * HDIM];  // R = reset*state hi
__device__ __nv_bfloat16 g_Rl[(size_t)BATCH * HDIM];

__device__ __forceinline__ uint32_t pack_bf16(__nv_bfloat16 a, __nv_bfloat16 b) {
    __nv_bfloat162 t; t.x = a; t.y = b;
    return *reinterpret_cast<uint32_t*>(&t);
}
__device__ __forceinline__ void split2(float x, float y, uint32_t& hp, uint32_t& lp) {
    __nv_bfloat16 hx = __float2bfloat16(x), hy = __float2bfloat16(y);
    __nv_bfloat16 lx = __float2bfloat16(x - __bfloat162float(hx));
    __nv_bfloat16 ly = __float2bfloat16(y - __bfloat162float(hy));
    hp = pack_bf16(hx, hy);
    lp = pack_bf16(lx, ly);
}

// --------------------------------------------------------------------------
__global__ void wtrans_kernel(const float* __restrict__ W, int ld, int off, int which) {
    __shared__ float tile[32][33];
    __nv_bfloat16* Oh = which ? g_W2h : g_W1h;
    __nv_bfloat16* Ol = which ? g_W2l : g_W1l;
    int tx = threadIdx.x, ty = threadIdx.y;
    int x0 = blockIdx.x * 32, y0 = blockIdx.y * 32;
#pragma unroll
    for (int j = 0; j < 32; j += 8)
        tile[ty + j][tx] = W[(y0 + ty + j) * ld + off + x0 + tx];
    __syncthreads();
#pragma unroll
    for (int j = 0; j < 32; j += 8) {
        float v = tile[tx][ty + j];
        int o = (x0 + ty + j) * HDIM + (y0 + tx);
        __nv_bfloat16 h = __float2bfloat16(v);
        Oh[o] = h;
        Ol[o] = __float2bfloat16(v - __bfloat162float(h));
    }
}

__global__ void psplit_kernel(const float* __restrict__ prev) {
    size_t i = ((size_t)blockIdx.x * 256 + threadIdx.x) * 4;
    float4 v = *reinterpret_cast<const float4*>(&prev[i]);
    uint32_t h01, l01, h23, l23;
    split2(v.x, v.y, h01, l01);
    split2(v.z, v.w, h23, l23);
    *reinterpret_cast<uint2*>(&g_Ph[i]) = make_uint2(h01, h23);
    *reinterpret_cast<uint2*>(&g_Pl[i]) = make_uint2(l01, l23);
}

// --------------------------------------------------------------------------
// GEMM: CTA 128x128, 8 warps (2M x 4N), warp tile 64x32, K-chunk 32,
// 2-stage cp.async. Inner loop processes mi in PAIRS with term-major
// interleaving: 24 MMAs between accumulator reuses of the same register.
// --------------------------------------------------------------------------
template <bool FIRST>
__global__ void __launch_bounds__(256, 2)
gemm_kernel(const float* __restrict__ inp, const float* __restrict__ prev,
            const float* __restrict__ mask, float* __restrict__ out) {
    extern __shared__ char smem_raw[];
    const uint32_t sb = smem_to_u32(smem_raw);

    const int tid   = threadIdx.x;
    const int wid   = tid >> 5;
    const int lane  = tid & 31;
    const int warpM = wid & 1;        // 2 warps over M (64 rows)
    const int warpN = wid >> 1;       // 4 warps over N (32 cols)
    const int m0 = blockIdx.x * M_TILE;
    const int n0 = blockIdx.y * N_TILE;

    const __nv_bfloat16* AHg = FIRST ? g_Ph  : g_Rh;
    const __nv_bfloat16* ALg = FIRST ? g_Pl  : g_Rl;
    const __nv_bfloat16* BHg = FIRST ? g_W1h : g_W2h;
    const __nv_bfloat16* BLg = FIRST ? g_W1l : g_W2l;

    const int rowq = tid >> 2;            // 0..63
    const int col8 = (tid & 3) * 8;

    auto issue_chunk = [&](int kc, int stage) {
        const uint32_t s0 = sb + stage * STG_BYTES;
#pragma unroll
        for (int r = 0; r < 2; r++) {
            const int row = rowq + r * 64;
            const size_t gA = (size_t)(m0 + row) * HDIM + kc * KT + col8;
            const size_t gB = (size_t)(n0 + row) * HDIM + kc * KT + col8;
            const uint32_t so = (uint32_t)(row * SA + col8) * 2;
            CP_ASYNC16(s0 + OFF_AH + so, AHg + gA);
            CP_ASYNC16(s0 + OFF_AL + so, ALg + gA);
            CP_ASYNC16(s0 + OFF_BH + so, BHg + gB);
            CP_ASYNC16(s0 + OFF_BL + so, BLg + gB);
        }
    };

    float acc[4][4][4];
#pragma unroll
    for (int i = 0; i < 4; i++)
#pragma unroll
        for (int j = 0; j < 4; j++)
#pragma unroll
            for (int k = 0; k < 4; k++) acc[i][j][k] = 0.f;

    issue_chunk(0, 0); CP_COMMIT();

    for (int c = 0; c < NC; c++) {
        if (c + 1 < NC) {
            issue_chunk(c + 1, (c + 1) & 1);
            CP_COMMIT();
            CP_WAIT1();
        } else {
            CP_WAIT0();
        }
        __syncthreads();

        const uint32_t s0  = sb + (c & 1) * STG_BYTES;
        const uint32_t sAh = s0 + OFF_AH, sAl = s0 + OFF_AL;
        const uint32_t sBh = s0 + OFF_BH, sBl = s0 + OFF_BL;

#pragma unroll
        for (int kb = 0; kb < KT; kb += 16) {
            // ---- B fragments: 4 n-subtiles x {b0,b1} per plane
            uint32_t bh[8], bl[8];
            const int q = lane >> 3;
#pragma unroll
            for (int p = 0; p < 2; p++) {
                const int nrow = warpN * 32 + (p * 2 + (q >> 1)) * 8 + (lane & 7);
                const int kcol = kb + (q & 1) * 8;
                const uint32_t off = (uint32_t)(nrow * SA + kcol) * 2;
                LDSM_X4(bh[4 * p], bh[4 * p + 1], bh[4 * p + 2], bh[4 * p + 3], sBh + off);
                LDSM_X4(bl[4 * p], bl[4 * p + 1], bl[4 * p + 2], bl[4 * p + 3], sBl + off);
            }
            // ---- process m-subtiles in pairs; term-major interleaved MMAs
            const int kcol = kb + ((lane >> 4) << 3);
#pragma unroll
            for (int mp = 0; mp < 2; mp++) {
                const int mi0 = mp * 2, mi1 = mp * 2 + 1;
                const int r0 = warpM * 64 + mi0 * 16 + (lane & 15);
                const int r1 = warpM * 64 + mi1 * 16 + (lane & 15);
                uint32_t a0h[4], a0l[4], a1h[4], a1l[4];
                {
                    const uint32_t o0 = (uint32_t)(r0 * SA + kcol) * 2;
                    const uint32_t o1 = (uint32_t)(r1 * SA + kcol) * 2;
                    LDSM_X4(a0h[0], a0h[1], a0h[2], a0h[3], sAh + o0);
                    LDSM_X4(a1h[0], a1h[1], a1h[2], a1h[3], sAh + o1);
                    LDSM_X4(a0l[0], a0l[1], a0l[2], a0l[3], sAl + o0);
                    LDSM_X4(a1l[0], a1l[1], a1l[2], a1l[3], sAl + o1);
                }
                // term 1: Ah @ Bh   (8 independent MMAs)
#pragma unroll
                for (int ni = 0; ni < 4; ni++) {
                    MMA_BF16(acc[mi0][ni], a0h, &bh[2 * ni]);
                    MMA_BF16(acc[mi1][ni], a1h, &bh[2 * ni]);
                }
                // term 2: Ah @ Bl
#pragma unroll
                for (int ni = 0; ni < 4; ni++) {
                    MMA_BF16(acc[mi0][ni], a0h, &bl[2 * ni]);
                    MMA_BF16(acc[mi1][ni], a1h, &bl[2 * ni]);
                }
                // term 3: Al @ Bh
#pragma unroll
                for (int ni = 0; ni < 4; ni++) {
                    MMA_BF16(acc[mi0][ni], a0l, &bh[2 * ni]);
                    MMA_BF16(acc[mi1][ni], a1l, &bh[2 * ni]);
                }
            }
        }
        __syncthreads();
    }

    // ---- epilogue ----
#pragma unroll
    for (int mi = 0; mi < 4; mi++) {
#pragma unroll
        for (int h = 0; h < 2; h++) {
            const int b = m0 + warpM * 64 + mi * 16 + h * 8 + (lane >> 2);
            float mval = 0.f;
            if (!FIRST) mval = __ldg(&mask[b]);
#pragma unroll
            for (int ni = 0; ni < 4; ni++) {
                const int n = n0 + warpN * 32 + ni * 8 + (lane & 3) * 2;
                const float v0 = acc[mi][ni][2 * h];
                const float v1 = acc[mi][ni][2 * h + 1];
                const float2 si = *reinterpret_cast<const float2*>(
                    &inp[(size_t)b * (3 * HDIM) + n]);
                if (FIRST) {
                    const float2 gi = *reinterpret_cast<const float2*>(
                        &inp[(size_t)b * (3 * HDIM) + 2 * HDIM + n]);
                    const float r0 = si.x / (1.f + __expf(-(v0 + gi.x)));
                    const float r1 = si.y / (1.f + __expf(-(v1 + gi.y)));
                    uint32_t hp, lp;
                    split2(r0, r1, hp, lp);
                    const size_t g = (size_t)b * HDIM + n;
                    *reinterpret_cast<uint32_t*>(&g_Rh[g]) = hp;
                    *reinterpret_cast<uint32_t*>(&g_Rl[g]) = lp;
                } else {
                    const float2 pv = *reinterpret_cast<const float2*>(
                        &prev[(size_t)b * HDIM + n]);
                    float2 o;
                    o.x = mval * (tanhf(v0 + si.x) + 1.f) + pv.x;
                    o.y = mval * (tanhf(v1 + si.y) + 1.f) + pv.y;
                    *reinterpret_cast<float2*>(&out[(size_t)b * HDIM + n]) = o;
                }
            }
        }
    }
}

// --------------------------------------------------------------------------
extern "C" void kernel_launch(void* const* d_in, const int* in_sizes, int n_in,
                              void* d_out, int out_size) {
    const float* inp  = (const float*)d_in[0];   // (B, 3H)
    const float* prev = (const float*)d_in[1];   // (B, H)
    const float* mask = (const float*)d_in[2];   // (B,)
    const float* Wur  = (const float*)d_in[3];   // (H, 2H)
    const float* U    = (const float*)d_in[4];   // (H, H)
    float* out = (float*)d_out;

    cudaFuncSetAttribute(gemm_kernel<true>,
                         cudaFuncAttributeMaxDynamicSharedMemorySize, SMEM_BYTES);
    cudaFuncSetAttribute(gemm_kernel<false>,
                         cudaFuncAttributeMaxDynamicSharedMemorySize, SMEM_BYTES);

    dim3 tb(32, 8), tg(HDIM / 32, HDIM / 32);
    wtrans_kernel<<<tg, tb>>>(Wur, 2 * HDIM, HDIM, 0);   // Wr = Wur[:, H:2H]
    wtrans_kernel<<<tg, tb>>>(U, HDIM, 0, 1);
    psplit_kernel<<<(BATCH * HDIM) / (256 * 4), 256>>>(prev);

    dim3 grid(BATCH / M_TILE, HDIM / N_TILE);
    gemm_kernel<true><<<grid, 256, SMEM_BYTES>>>(inp, prev, mask, out);
    gemm_kernel<false><<<grid, 256, SMEM_BYTES>>>(inp, prev, mask, out);
}

// round 5
// speedup vs baseline: 1.3563x; 1.0202x over previous
#include <cuda_runtime.h>
#include <cuda_bf16.h>
#include <cstdint>

// ============================================================================
// GGRUCell on GB300 — HMMA bf16 hi/lo-split GEMMs.
// R5: B (weights) moved OUT of smem — pre-packed in mma-fragment-linear
// layout in global, fetched by ldg.128 from L2/L1. Smem holds A planes only.
//
//   R   = sigmoid(prev @ Wr + inp[:,2H:]) * inp[:,:H]
//   out = mask * (tanh(R @ U + inp[:,:H]) + 1) + prev   (update gate cancels)
// fp32 GEMM == Ah@Bh + Ah@Bl + Al@Bh with bf16 planes (rel_err ~2e-6).
// ============================================================================

#define HDIM   1024
#define BATCH  16384

static constexpr int M_TILE = 128;
static constexpr int N_TILE = 128;
static constexpr int KT     = 32;            // K-chunk
static constexpr int NC     = HDIM / KT;     // 32 chunks
static constexpr int SA     = 40;            // padded smem row stride (bf16)

static constexpr int PLANE_BYTES = 128 * SA * 2;        // 10240
static constexpr int OFF_AH = 0;
static constexpr int OFF_AL = PLANE_BYTES;
static constexpr int STG_BYTES = 2 * PLANE_BYTES;       // 20480
static constexpr int SMEM_BYTES = 2 * STG_BYTES;        // 40960

// --------------------------------------------------------------------------
__device__ __forceinline__ uint32_t smem_to_u32(const void* p) {
    uint32_t a;
    asm("{ .reg .u64 t; cvta.to.shared.u64 t, %1; cvt.u32.u64 %0, t; }" : "=r"(a) : "l"(p));
    return a;
}
#define CP_ASYNC16(s, g) \
    asm volatile("cp.async.cg.shared.global [%0], [%1], 16;" :: "r"(s), "l"(g) : "memory")
#define CP_COMMIT() asm volatile("cp.async.commit_group;" ::: "memory")
#define CP_WAIT1()  asm volatile("cp.async.wait_group 1;" ::: "memory")
#define CP_WAIT0()  asm volatile("cp.async.wait_group 0;" ::: "memory")

#define LDSM_X4(r0, r1, r2, r3, addr) \
    asm volatile("ldmatrix.sync.aligned.m8n8.x4.shared.b16 {%0,%1,%2,%3}, [%4];" \
                 : "=r"(r0), "=r"(r1), "=r"(r2), "=r"(r3) : "r"(addr))

#define MMA_BF16_2(d, a, b0, b1) \
    asm volatile("mma.sync.aligned.m16n8k16.row.col.f32.bf16.bf16.f32 " \
                 "{%0,%1,%2,%3}, {%4,%5,%6,%7}, {%8,%9}, {%0,%1,%2,%3};" \
                 : "+f"((d)[0]), "+f"((d)[1]), "+f"((d)[2]), "+f"((d)[3]) \
                 : "r"((a)[0]), "r"((a)[1]), "r"((a)[2]), "r"((a)[3]), \
                   "r"(b0), "r"(b1))

// --------------------------------------------------------------------------
// Scratch (no cudaMalloc allowed)
// --------------------------------------------------------------------------
// B fragment-linear planes: index ((n8*NC + k32)*32 + lane) -> uint4 holding
// {b0,b1} for kb=0 (k32*32..+15) and {b0,b1} for kb=1 (+16..+31) per the
// mma.m16n8k16 .col B layout (thread t: n = t/4, k = 2*(t%4)+{0,1}(+8..)).
__device__ uint4 g_W1hf[(HDIM / 8) * NC * 32];
__device__ uint4 g_W1lf[(HDIM / 8) * NC * 32];
__device__ uint4 g_W2hf[(HDIM / 8) * NC * 32];
__device__ uint4 g_W2lf[(HDIM / 8) * NC * 32];
__device__ __nv_bfloat16 g_Ph[(size_t)BATCH * HDIM];  // prev hi
__device__ __nv_bfloat16 g_Pl[(size_t)BATCH * HDIM];
__device__ __nv_bfloat16 g_Rh[(size_t)BATCH * HDIM];  // R = reset*state hi
__device__ __nv_bfloat16 g_Rl[(size_t)BATCH * HDIM];

__device__ __forceinline__ uint32_t pack_bf16(__nv_bfloat16 a, __nv_bfloat16 b) {
    __nv_bfloat162 t; t.x = a; t.y = b;
    return *reinterpret_cast<uint32_t*>(&t);
}
__device__ __forceinline__ void split2(float x, float y, uint32_t& hp, uint32_t& lp) {
    __nv_bfloat16 hx = __float2bfloat16(x), hy = __float2bfloat16(y);
    __nv_bfloat16 lx = __float2bfloat16(x - __bfloat162float(hx));
    __nv_bfloat16 ly = __float2bfloat16(y - __bfloat162float(hy));
    hp = pack_bf16(hx, hy);
    lp = pack_bf16(lx, ly);
}

// --------------------------------------------------------------------------
// Weight -> fragment-linear hi/lo planes.
// One thread per (n8, k32, lane) slot; writes one uint4 per plane.
// --------------------------------------------------------------------------
__global__ void wtrans_frag(const float* __restrict__ W, int ld, int off, int which) {
    const int t    = blockIdx.x * 256 + threadIdx.x;     // == output index
    const int lane = t & 31;
    const int k32  = (t >> 5) & (NC - 1);
    const int n8   = t >> 10;
    const int n    = n8 * 8 + (lane >> 2);
    const int kb   = k32 * 32 + 2 * (lane & 3);
    uint32_t h[4], l[4];
#pragma unroll
    for (int w = 0; w < 4; w++) {
        const int k = kb + 8 * w;
        const float v0 = W[(size_t)k * ld + off + n];
        const float v1 = W[(size_t)(k + 1) * ld + off + n];
        split2(v0, v1, h[w], l[w]);
    }
    uint4* Fh = which ? g_W2hf : g_W1hf;
    uint4* Fl = which ? g_W2lf : g_W1lf;
    Fh[t] = make_uint4(h[0], h[1], h[2], h[3]);
    Fl[t] = make_uint4(l[0], l[1], l[2], l[3]);
}

// --------------------------------------------------------------------------
__global__ void psplit_kernel(const float* __restrict__ prev) {
    size_t i = ((size_t)blockIdx.x * 256 + threadIdx.x) * 4;
    float4 v = *reinterpret_cast<const float4*>(&prev[i]);
    uint32_t h01, l01, h23, l23;
    split2(v.x, v.y, h01, l01);
    split2(v.z, v.w, h23, l23);
    *reinterpret_cast<uint2*>(&g_Ph[i]) = make_uint2(h01, h23);
    *reinterpret_cast<uint2*>(&g_Pl[i]) = make_uint2(l01, l23);
}

// --------------------------------------------------------------------------
// GEMM: CTA 128x128, 8 warps (2M x 4N), warp tile 64x32, K-chunk 32.
// A planes via cp.async + LDSM (smem); B fragments via ldg.128 from L2.
// --------------------------------------------------------------------------
template <bool FIRST>
__global__ void __launch_bounds__(256, 2)
gemm_kernel(const float* __restrict__ inp, const float* __restrict__ prev,
            const float* __restrict__ mask, float* __restrict__ out) {
    extern __shared__ char smem_raw[];
    const uint32_t sb = smem_to_u32(smem_raw);

    const int tid   = threadIdx.x;
    const int wid   = tid >> 5;
    const int lane  = tid & 31;
    const int warpM = wid & 1;        // 2 warps over M (64 rows)
    const int warpN = wid >> 1;       // 4 warps over N (32 cols)
    const int m0 = blockIdx.x * M_TILE;
    const int n0 = blockIdx.y * N_TILE;

    const __nv_bfloat16* AHg = FIRST ? g_Ph : g_Rh;
    const __nv_bfloat16* ALg = FIRST ? g_Pl : g_Rl;
    const uint4* __restrict__ BHf = FIRST ? g_W1hf : g_W2hf;
    const uint4* __restrict__ BLf = FIRST ? g_W1lf : g_W2lf;
    const int nb = (n0 >> 3) + warpN * 4;     // base n8 tile for this warp

    const int rowq = tid >> 2;            // 0..63
    const int col8 = (tid & 3) * 8;

    auto issue_chunk = [&](int kc, int stage) {
        const uint32_t s0 = sb + stage * STG_BYTES;
#pragma unroll
        for (int r = 0; r < 2; r++) {
            const int row = rowq + r * 64;
            const size_t gA = (size_t)(m0 + row) * HDIM + kc * KT + col8;
            const uint32_t so = (uint32_t)(row * SA + col8) * 2;
            CP_ASYNC16(s0 + OFF_AH + so, AHg + gA);
            CP_ASYNC16(s0 + OFF_AL + so, ALg + gA);
        }
    };

    float acc[4][4][4];
#pragma unroll
    for (int i = 0; i < 4; i++)
#pragma unroll
        for (int j = 0; j < 4; j++)
#pragma unroll
            for (int k = 0; k < 4; k++) acc[i][j][k] = 0.f;

    issue_chunk(0, 0); CP_COMMIT();

    for (int c = 0; c < NC; c++) {
        if (c + 1 < NC) {
            issue_chunk(c + 1, (c + 1) & 1);
            CP_COMMIT();
            CP_WAIT1();
        } else {
            CP_WAIT0();
        }
        __syncthreads();

        // ---- B fragments for the whole chunk: 8 coalesced ldg.128 (L2/L1)
        uint4 Bh4[4], Bl4[4];
#pragma unroll
        for (int ni = 0; ni < 4; ni++) {
            const int idx = ((nb + ni) * NC + c) * 32 + lane;
            Bh4[ni] = __ldg(&BHf[idx]);
            Bl4[ni] = __ldg(&BLf[idx]);
        }

        const uint32_t s0  = sb + (c & 1) * STG_BYTES;
        const uint32_t sAh = s0 + OFF_AH, sAl = s0 + OFF_AL;

#pragma unroll
        for (int kb2 = 0; kb2 < 2; kb2++) {
            const int kcol = kb2 * 16 + ((lane >> 4) << 3);
#pragma unroll
            for (int mp = 0; mp < 2; mp++) {
                const int mi0 = mp * 2, mi1 = mp * 2 + 1;
                const int r0 = warpM * 64 + mi0 * 16 + (lane & 15);
                const int r1 = warpM * 64 + mi1 * 16 + (lane & 15);
                uint32_t a0h[4], a0l[4], a1h[4], a1l[4];
                {
                    const uint32_t o0 = (uint32_t)(r0 * SA + kcol) * 2;
                    const uint32_t o1 = (uint32_t)(r1 * SA + kcol) * 2;
                    LDSM_X4(a0h[0], a0h[1], a0h[2], a0h[3], sAh + o0);
                    LDSM_X4(a1h[0], a1h[1], a1h[2], a1h[3], sAh + o1);
                    LDSM_X4(a0l[0], a0l[1], a0l[2], a0l[3], sAl + o0);
                    LDSM_X4(a1l[0], a1l[1], a1l[2], a1l[3], sAl + o1);
                }
#pragma unroll
                for (int ni = 0; ni < 4; ni++) {
                    const uint32_t bh0 = kb2 ? Bh4[ni].z : Bh4[ni].x;
                    const uint32_t bh1 = kb2 ? Bh4[ni].w : Bh4[ni].y;
                    MMA_BF16_2(acc[mi0][ni], a0h, bh0, bh1);
                    MMA_BF16_2(acc[mi1][ni], a1h, bh0, bh1);
                }
#pragma unroll
                for (int ni = 0; ni < 4; ni++) {
                    const uint32_t bl0 = kb2 ? Bl4[ni].z : Bl4[ni].x;
                    const uint32_t bl1 = kb2 ? Bl4[ni].w : Bl4[ni].y;
                    MMA_BF16_2(acc[mi0][ni], a0h, bl0, bl1);
                    MMA_BF16_2(acc[mi1][ni], a1h, bl0, bl1);
                }
#pragma unroll
                for (int ni = 0; ni < 4; ni++) {
                    const uint32_t bh0 = kb2 ? Bh4[ni].z : Bh4[ni].x;
                    const uint32_t bh1 = kb2 ? Bh4[ni].w : Bh4[ni].y;
                    MMA_BF16_2(acc[mi0][ni], a0l, bh0, bh1);
                    MMA_BF16_2(acc[mi1][ni], a1l, bh0, bh1);
                }
            }
        }
        __syncthreads();
    }

    // ---- epilogue ----
#pragma unroll
    for (int mi = 0; mi < 4; mi++) {
#pragma unroll
        for (int h = 0; h < 2; h++) {
            const int b = m0 + warpM * 64 + mi * 16 + h * 8 + (lane >> 2);
            float mval = 0.f;
            if (!FIRST) mval = __ldg(&mask[b]);
#pragma unroll
            for (int ni = 0; ni < 4; ni++) {
                const int n = n0 + warpN * 32 + ni * 8 + (lane & 3) * 2;
                const float v0 = acc[mi][ni][2 * h];
                const float v1 = acc[mi][ni][2 * h + 1];
                const float2 si = *reinterpret_cast<const float2*>(
                    &inp[(size_t)b * (3 * HDIM) + n]);
                if (FIRST) {
                    const float2 gi = *reinterpret_cast<const float2*>(
                        &inp[(size_t)b * (3 * HDIM) + 2 * HDIM + n]);
                    const float r0 = si.x / (1.f + __expf(-(v0 + gi.x)));
                    const float r1 = si.y / (1.f + __expf(-(v1 + gi.y)));
                    uint32_t hp, lp;
                    split2(r0, r1, hp, lp);
                    const size_t g = (size_t)b * HDIM + n;
                    *reinterpret_cast<uint32_t*>(&g_Rh[g]) = hp;
                    *reinterpret_cast<uint32_t*>(&g_Rl[g]) = lp;
                } else {
                    const float2 pv = *reinterpret_cast<const float2*>(
                        &prev[(size_t)b * HDIM + n]);
                    float2 o;
                    o.x = mval * (tanhf(v0 + si.x) + 1.f) + pv.x;
                    o.y = mval * (tanhf(v1 + si.y) + 1.f) + pv.y;
                    *reinterpret_cast<float2*>(&out[(size_t)b * HDIM + n]) = o;
                }
            }
        }
    }
}

// --------------------------------------------------------------------------
extern "C" void kernel_launch(void* const* d_in, const int* in_sizes, int n_in,
                              void* d_out, int out_size) {
    const float* inp  = (const float*)d_in[0];   // (B, 3H)
    const float* prev = (const float*)d_in[1];   // (B, H)
    const float* mask = (const float*)d_in[2];   // (B,)
    const float* Wur  = (const float*)d_in[3];   // (H, 2H)
    const float* U    = (const float*)d_in[4];   // (H, H)
    float* out = (float*)d_out;

    cudaFuncSetAttribute(gemm_kernel<true>,
                         cudaFuncAttributeMaxDynamicSharedMemorySize, SMEM_BYTES);
    cudaFuncSetAttribute(gemm_kernel<false>,
                         cudaFuncAttributeMaxDynamicSharedMemorySize, SMEM_BYTES);

    const int frag_slots = (HDIM / 8) * NC * 32;           // 131072
    wtrans_frag<<<frag_slots / 256, 256>>>(Wur, 2 * HDIM, HDIM, 0);  // Wr
    wtrans_frag<<<frag_slots / 256, 256>>>(U, HDIM, 0, 1);
    psplit_kernel<<<(BATCH * HDIM) / (256 * 4), 256>>>(prev);

    dim3 grid(BATCH / M_TILE, HDIM / N_TILE);
    gemm_kernel<true><<<grid, 256, SMEM_BYTES>>>(inp, prev, mask, out);
    gemm_kernel<false><<<grid, 256, SMEM_BYTES>>>(inp, prev, mask, out);
}

// round 6
// speedup vs baseline: 2.1067x; 1.5533x over previous
#include <cuda_runtime.h>
#include <cuda_fp16.h>
#include <cstdint>

// ============================================================================
// GGRUCell on GB300 — HMMA fp16 2-term split GEMMs.
// R6: fp16 planes (11-bit mantissa) let us drop the A-residual term:
//     fp32 GEMM ~= Ah@Bh + Ah@Bl   (2 MMAs per tile, was 3)
// A: single fp16 plane in smem (cp.async, 4 stages). B: hi/lo fp16
// fragment-linear planes in global (L2-resident), ldg.128 per chunk.
//
//   R   = sigmoid(prev @ Wr + inp[:,2H:]) * inp[:,:H]
//   out = mask * (tanh(R @ U + inp[:,:H]) + 1) + prev   (update gate cancels)
// ============================================================================

#define HDIM   1024
#define BATCH  16384

static constexpr int M_TILE = 128;
static constexpr int N_TILE = 128;
static constexpr int KT     = 32;            // K-chunk
static constexpr int NC     = HDIM / KT;     // 32 chunks
static constexpr int SA     = 40;            // padded smem row stride (fp16)
static constexpr int STAGES = 4;

static constexpr int PLANE_BYTES = 128 * SA * 2;        // 10240
static constexpr int SMEM_BYTES  = STAGES * PLANE_BYTES; // 40960

// --------------------------------------------------------------------------
__device__ __forceinline__ uint32_t smem_to_u32(const void* p) {
    uint32_t a;
    asm("{ .reg .u64 t; cvta.to.shared.u64 t, %1; cvt.u32.u64 %0, t; }" : "=r"(a) : "l"(p));
    return a;
}
#define CP_ASYNC16(s, g) \
    asm volatile("cp.async.cg.shared.global [%0], [%1], 16;" :: "r"(s), "l"(g) : "memory")
#define CP_COMMIT() asm volatile("cp.async.commit_group;" ::: "memory")
#define CP_WAIT2()  asm volatile("cp.async.wait_group 2;" ::: "memory")

#define LDSM_X4(r0, r1, r2, r3, addr) \
    asm volatile("ldmatrix.sync.aligned.m8n8.x4.shared.b16 {%0,%1,%2,%3}, [%4];" \
                 : "=r"(r0), "=r"(r1), "=r"(r2), "=r"(r3) : "r"(addr))

#define MMA_F16_2(d, a, b0, b1) \
    asm volatile("mma.sync.aligned.m16n8k16.row.col.f32.f16.f16.f32 " \
                 "{%0,%1,%2,%3}, {%4,%5,%6,%7}, {%8,%9}, {%0,%1,%2,%3};" \
                 : "+f"((d)[0]), "+f"((d)[1]), "+f"((d)[2]), "+f"((d)[3]) \
                 : "r"((a)[0]), "r"((a)[1]), "r"((a)[2]), "r"((a)[3]), \
                   "r"(b0), "r"(b1))

// --------------------------------------------------------------------------
// Scratch (no cudaMalloc allowed)
// --------------------------------------------------------------------------
// B fragment-linear planes: index ((n8*NC + k32)*32 + lane) -> uint4 holding
// {b0,b1} for kb2=0 and {b0,b1} for kb2=1 per the m16n8k16 .col B layout
// (thread t: n = t/4, k = 2*(t%4)+{0,1}, +8, +16, +24).
__device__ uint4 g_W1hf[(HDIM / 8) * NC * 32];
__device__ uint4 g_W1lf[(HDIM / 8) * NC * 32];
__device__ uint4 g_W2hf[(HDIM / 8) * NC * 32];
__device__ uint4 g_W2lf[(HDIM / 8) * NC * 32];
__device__ __half g_Ph[(size_t)BATCH * HDIM];   // prev, fp16
__device__ __half g_Rh[(size_t)BATCH * HDIM];   // R = reset*state, fp16

__device__ __forceinline__ uint32_t pack_h2(__half a, __half b) {
    __half2 t; t.x = a; t.y = b;
    return *reinterpret_cast<uint32_t*>(&t);
}
// fp16 hi/lo split of a pair of floats
__device__ __forceinline__ void split2h(float x, float y, uint32_t& hp, uint32_t& lp) {
    __half hx = __float2half(x), hy = __float2half(y);
    __half lx = __float2half(x - __half2float(hx));
    __half ly = __float2half(y - __half2float(hy));
    hp = pack_h2(hx, hy);
    lp = pack_h2(lx, ly);
}

// --------------------------------------------------------------------------
// Weight -> fragment-linear hi/lo fp16 planes.
// --------------------------------------------------------------------------
__global__ void wtrans_frag(const float* __restrict__ W, int ld, int off, int which) {
    const int t    = blockIdx.x * 256 + threadIdx.x;     // output index
    const int lane = t & 31;
    const int k32  = (t >> 5) & (NC - 1);
    const int n8   = t >> 10;
    const int n    = n8 * 8 + (lane >> 2);
    const int kb   = k32 * 32 + 2 * (lane & 3);
    uint32_t h[4], l[4];
#pragma unroll
    for (int w = 0; w < 4; w++) {
        const int k = kb + 8 * w;
        const float v0 = W[(size_t)k * ld + off + n];
        const float v1 = W[(size_t)(k + 1) * ld + off + n];
        split2h(v0, v1, h[w], l[w]);
    }
    uint4* Fh = which ? g_W2hf : g_W1hf;
    uint4* Fl = which ? g_W2lf : g_W1lf;
    Fh[t] = make_uint4(h[0], h[1], h[2], h[3]);
    Fl[t] = make_uint4(l[0], l[1], l[2], l[3]);
}

// --------------------------------------------------------------------------
__global__ void psplit_kernel(const float* __restrict__ prev) {
    size_t i = ((size_t)blockIdx.x * 256 + threadIdx.x) * 4;
    float4 v = *reinterpret_cast<const float4*>(&prev[i]);
    uint32_t p01 = pack_h2(__float2half(v.x), __float2half(v.y));
    uint32_t p23 = pack_h2(__float2half(v.z), __float2half(v.w));
    *reinterpret_cast<uint2*>(&g_Ph[i]) = make_uint2(p01, p23);
}

// --------------------------------------------------------------------------
// GEMM: CTA 128x128, 8 warps (2M x 4N), warp tile 64x32, K-chunk 32.
// A single fp16 plane via cp.async (4 stages) + LDSM; B frags via ldg.128.
// --------------------------------------------------------------------------
template <bool FIRST>
__global__ void __launch_bounds__(256, 2)
gemm_kernel(const float* __restrict__ inp, const float* __restrict__ prev,
            const float* __restrict__ mask, float* __restrict__ out) {
    extern __shared__ char smem_raw[];
    const uint32_t sb = smem_to_u32(smem_raw);

    const int tid   = threadIdx.x;
    const int wid   = tid >> 5;
    const int lane  = tid & 31;
    const int warpM = wid & 1;        // 2 warps over M (64 rows)
    const int warpN = wid >> 1;       // 4 warps over N (32 cols)
    const int m0 = blockIdx.x * M_TILE;
    const int n0 = blockIdx.y * N_TILE;

    const __half* AHg = FIRST ? g_Ph : g_Rh;
    const uint4* __restrict__ BHf = FIRST ? g_W1hf : g_W2hf;
    const uint4* __restrict__ BLf = FIRST ? g_W1lf : g_W2lf;
    const int nb = (n0 >> 3) + warpN * 4;     // base n8 tile for this warp

    auto issue_chunk = [&](int kc, int stage) {
        const uint32_t s0 = sb + stage * PLANE_BYTES;
#pragma unroll
        for (int i = 0; i < 2; i++) {
            const int g   = tid + i * 256;    // 512 granules of 16B
            const int row = g >> 2;
            const int ce  = (g & 3) * 8;
            const size_t gA = (size_t)(m0 + row) * HDIM + kc * KT + ce;
            const uint32_t so = (uint32_t)(row * SA + ce) * 2;
            CP_ASYNC16(s0 + so, AHg + gA);
        }
    };

    float acc[4][4][4];
#pragma unroll
    for (int i = 0; i < 4; i++)
#pragma unroll
        for (int j = 0; j < 4; j++)
#pragma unroll
            for (int k = 0; k < 4; k++) acc[i][j][k] = 0.f;

    issue_chunk(0, 0); CP_COMMIT();
    issue_chunk(1, 1); CP_COMMIT();
    issue_chunk(2, 2); CP_COMMIT();

    for (int c = 0; c < NC; c++) {
        // B fragments for this chunk: 8 ldg.128 from L2 (independent of smem)
        uint4 Bh4[4], Bl4[4];
#pragma unroll
        for (int ni = 0; ni < 4; ni++) {
            const int idx = ((nb + ni) * NC + c) * 32 + lane;
            Bh4[ni] = __ldg(&BHf[idx]);
            Bl4[ni] = __ldg(&BLf[idx]);
        }

        CP_WAIT2();            // chunk c landed (c+1, c+2 may be pending)
        __syncthreads();       // all warps' cp.async data visible
        if (c + 3 < NC) {      // refill stage (c+3)&3 (safe: post-barrier)
            issue_chunk(c + 3, (c + 3) & 3);
            CP_COMMIT();
        }

        const uint32_t sAh = sb + (c & 3) * PLANE_BYTES;

#pragma unroll
        for (int kb2 = 0; kb2 < 2; kb2++) {
            const int kcol = kb2 * 16 + ((lane >> 4) << 3);
#pragma unroll
            for (int mp = 0; mp < 2; mp++) {
                const int mi0 = mp * 2, mi1 = mp * 2 + 1;
                const int r0 = warpM * 64 + mi0 * 16 + (lane & 15);
                const int r1 = warpM * 64 + mi1 * 16 + (lane & 15);
                uint32_t a0[4], a1[4];
                {
                    const uint32_t o0 = (uint32_t)(r0 * SA + kcol) * 2;
                    const uint32_t o1 = (uint32_t)(r1 * SA + kcol) * 2;
                    LDSM_X4(a0[0], a0[1], a0[2], a0[3], sAh + o0);
                    LDSM_X4(a1[0], a1[1], a1[2], a1[3], sAh + o1);
                }
#pragma unroll
                for (int ni = 0; ni < 4; ni++) {
                    const uint32_t bh0 = kb2 ? Bh4[ni].z : Bh4[ni].x;
                    const uint32_t bh1 = kb2 ? Bh4[ni].w : Bh4[ni].y;
                    MMA_F16_2(acc[mi0][ni], a0, bh0, bh1);
                    MMA_F16_2(acc[mi1][ni], a1, bh0, bh1);
                }
#pragma unroll
                for (int ni = 0; ni < 4; ni++) {
                    const uint32_t bl0 = kb2 ? Bl4[ni].z : Bl4[ni].x;
                    const uint32_t bl1 = kb2 ? Bl4[ni].w : Bl4[ni].y;
                    MMA_F16_2(acc[mi0][ni], a0, bl0, bl1);
                    MMA_F16_2(acc[mi1][ni], a1, bl0, bl1);
                }
            }
        }
    }

    // ---- epilogue ----
#pragma unroll
    for (int mi = 0; mi < 4; mi++) {
#pragma unroll
        for (int h = 0; h < 2; h++) {
            const int b = m0 + warpM * 64 + mi * 16 + h * 8 + (lane >> 2);
            float mval = 0.f;
            if (!FIRST) mval = __ldg(&mask[b]);
#pragma unroll
            for (int ni = 0; ni < 4; ni++) {
                const int n = n0 + warpN * 32 + ni * 8 + (lane & 3) * 2;
                const float v0 = acc[mi][ni][2 * h];
                const float v1 = acc[mi][ni][2 * h + 1];
                const float2 si = *reinterpret_cast<const float2*>(
                    &inp[(size_t)b * (3 * HDIM) + n]);
                if (FIRST) {
                    const float2 gi = *reinterpret_cast<const float2*>(
                        &inp[(size_t)b * (3 * HDIM) + 2 * HDIM + n]);
                    const float r0 = si.x / (1.f + __expf(-(v0 + gi.x)));
                    const float r1 = si.y / (1.f + __expf(-(v1 + gi.y)));
                    *reinterpret_cast<uint32_t*>(&g_Rh[(size_t)b * HDIM + n]) =
                        pack_h2(__float2half(r0), __float2half(r1));
                } else {
                    const float2 pv = *reinterpret_cast<const float2*>(
                        &prev[(size_t)b * HDIM + n]);
                    float2 o;
                    o.x = mval * (tanhf(v0 + si.x) + 1.f) + pv.x;
                    o.y = mval * (tanhf(v1 + si.y) + 1.f) + pv.y;
                    *reinterpret_cast<float2*>(&out[(size_t)b * HDIM + n]) = o;
                }
            }
        }
    }
}

// --------------------------------------------------------------------------
extern "C" void kernel_launch(void* const* d_in, const int* in_sizes, int n_in,
                              void* d_out, int out_size) {
    const float* inp  = (const float*)d_in[0];   // (B, 3H)
    const float* prev = (const float*)d_in[1];   // (B, H)
    const float* mask = (const float*)d_in[2];   // (B,)
    const float* Wur  = (const float*)d_in[3];   // (H, 2H)
    const float* U    = (const float*)d_in[4];   // (H, H)
    float* out = (float*)d_out;

    cudaFuncSetAttribute(gemm_kernel<true>,
                         cudaFuncAttributeMaxDynamicSharedMemorySize, SMEM_BYTES);
    cudaFuncSetAttribute(gemm_kernel<false>,
                         cudaFuncAttributeMaxDynamicSharedMemorySize, SMEM_BYTES);

    const int frag_slots = (HDIM / 8) * NC * 32;           // 131072
    wtrans_frag<<<frag_slots / 256, 256>>>(Wur, 2 * HDIM, HDIM, 0);  // Wr
    wtrans_frag<<<frag_slots / 256, 256>>>(U, HDIM, 0, 1);
    psplit_kernel<<<(BATCH * HDIM) / (256 * 4), 256>>>(prev);

    dim3 grid(BATCH / M_TILE, HDIM / N_TILE);
    gemm_kernel<true><<<grid, 256, SMEM_BYTES>>>(inp, prev, mask, out);
    gemm_kernel<false><<<grid, 256, SMEM_BYTES>>>(inp, prev, mask, out);
}

// round 7
// speedup vs baseline: 2.5903x; 1.2295x over previous
#include <cuda_runtime.h>
#include <cuda_fp16.h>
#include <cstdint>

// ============================================================================
// GGRUCell on GB300 — HMMA fp16 single-term GEMMs (1 MMA per tile).
// R7: pure fp16 A and B (no residual terms). Expected rel_err ~1.3e-4.
// Warp grid 4M x 2N (warp tile 32x64) to halve A-LDSM redundancy so the
// smem crossbar stays under the halved MMA floor.
//
//   R   = sigmoid(prev @ Wr + inp[:,2H:]) * inp[:,:H]
//   out = mask * (tanh(R @ U + inp[:,:H]) + 1) + prev   (update gate cancels)
// ============================================================================

#define HDIM   1024
#define BATCH  16384

static constexpr int M_TILE = 128;
static constexpr int N_TILE = 128;
static constexpr int KT     = 32;            // K-chunk
static constexpr int NC     = HDIM / KT;     // 32 chunks
static constexpr int SA     = 40;            // padded smem row stride (fp16)
static constexpr int STAGES = 4;

static constexpr int PLANE_BYTES = 128 * SA * 2;         // 10240
static constexpr int SMEM_BYTES  = STAGES * PLANE_BYTES; // 40960

// --------------------------------------------------------------------------
__device__ __forceinline__ uint32_t smem_to_u32(const void* p) {
    uint32_t a;
    asm("{ .reg .u64 t; cvta.to.shared.u64 t, %1; cvt.u32.u64 %0, t; }" : "=r"(a) : "l"(p));
    return a;
}
#define CP_ASYNC16(s, g) \
    asm volatile("cp.async.cg.shared.global [%0], [%1], 16;" :: "r"(s), "l"(g) : "memory")
#define CP_COMMIT() asm volatile("cp.async.commit_group;" ::: "memory")
#define CP_WAIT2()  asm volatile("cp.async.wait_group 2;" ::: "memory")

#define LDSM_X4(r0, r1, r2, r3, addr) \
    asm volatile("ldmatrix.sync.aligned.m8n8.x4.shared.b16 {%0,%1,%2,%3}, [%4];" \
                 : "=r"(r0), "=r"(r1), "=r"(r2), "=r"(r3) : "r"(addr))

#define MMA_F16_2(d, a, b0, b1) \
    asm volatile("mma.sync.aligned.m16n8k16.row.col.f32.f16.f16.f32 " \
                 "{%0,%1,%2,%3}, {%4,%5,%6,%7}, {%8,%9}, {%0,%1,%2,%3};" \
                 : "+f"((d)[0]), "+f"((d)[1]), "+f"((d)[2]), "+f"((d)[3]) \
                 : "r"((a)[0]), "r"((a)[1]), "r"((a)[2]), "r"((a)[3]), \
                   "r"(b0), "r"(b1))

// --------------------------------------------------------------------------
// Scratch (no cudaMalloc allowed)
// --------------------------------------------------------------------------
// B fragment-linear planes: index ((n8*NC + k32)*32 + lane) -> uint4 holding
// {b0,b1} for kb2=0 and {b0,b1} for kb2=1 per the m16n8k16 .col B layout
// (thread t: n = t/4, k = 2*(t%4)+{0,1}, +8, +16, +24).
__device__ uint4 g_W1f[(HDIM / 8) * NC * 32];
__device__ uint4 g_W2f[(HDIM / 8) * NC * 32];
__device__ __half g_Ph[(size_t)BATCH * HDIM];   // prev, fp16
__device__ __half g_Rh[(size_t)BATCH * HDIM];   // R = reset*state, fp16

__device__ __forceinline__ uint32_t pack_h2(__half a, __half b) {
    __half2 t; t.x = a; t.y = b;
    return *reinterpret_cast<uint32_t*>(&t);
}

// --------------------------------------------------------------------------
// Weight -> fragment-linear fp16 plane.
// --------------------------------------------------------------------------
__global__ void wtrans_frag(const float* __restrict__ W, int ld, int off, int which) {
    const int t    = blockIdx.x * 256 + threadIdx.x;     // output index
    const int lane = t & 31;
    const int k32  = (t >> 5) & (NC - 1);
    const int n8   = t >> 10;
    const int n    = n8 * 8 + (lane >> 2);
    const int kb   = k32 * 32 + 2 * (lane & 3);
    uint32_t h[4];
#pragma unroll
    for (int w = 0; w < 4; w++) {
        const int k = kb + 8 * w;
        const float v0 = W[(size_t)k * ld + off + n];
        const float v1 = W[(size_t)(k + 1) * ld + off + n];
        h[w] = pack_h2(__float2half(v0), __float2half(v1));
    }
    uint4* F = which ? g_W2f : g_W1f;
    F[t] = make_uint4(h[0], h[1], h[2], h[3]);
}

// --------------------------------------------------------------------------
__global__ void psplit_kernel(const float* __restrict__ prev) {
    size_t i = ((size_t)blockIdx.x * 256 + threadIdx.x) * 4;
    float4 v = *reinterpret_cast<const float4*>(&prev[i]);
    uint32_t p01 = pack_h2(__float2half(v.x), __float2half(v.y));
    uint32_t p23 = pack_h2(__float2half(v.z), __float2half(v.w));
    *reinterpret_cast<uint2*>(&g_Ph[i]) = make_uint2(p01, p23);
}

// --------------------------------------------------------------------------
// GEMM: CTA 128x128, 8 warps (4M x 2N), warp tile 32x64, K-chunk 32.
// A fp16 plane via cp.async (4 stages) + LDSM; B frags via ldg.128 from L2.
// --------------------------------------------------------------------------
template <bool FIRST>
__global__ void __launch_bounds__(256, 2)
gemm_kernel(const float* __restrict__ inp, const float* __restrict__ prev,
            const float* __restrict__ mask, float* __restrict__ out) {
    extern __shared__ char smem_raw[];
    const uint32_t sb = smem_to_u32(smem_raw);

    const int tid   = threadIdx.x;
    const int wid   = tid >> 5;
    const int lane  = tid & 31;
    const int warpM = wid >> 1;       // 4 warps over M (32 rows each)
    const int warpN = wid & 1;        // 2 warps over N (64 cols each)
    const int m0 = blockIdx.x * M_TILE;
    const int n0 = blockIdx.y * N_TILE;

    const __half* AHg = FIRST ? g_Ph : g_Rh;
    const uint4* __restrict__ BF = FIRST ? g_W1f : g_W2f;
    const int nb = (n0 >> 3) + warpN * 8;     // base n8 tile for this warp

    auto issue_chunk = [&](int kc, int stage) {
        const uint32_t s0 = sb + stage * PLANE_BYTES;
#pragma unroll
        for (int i = 0; i < 2; i++) {
            const int g   = tid + i * 256;    // 512 granules of 16B
            const int row = g >> 2;
            const int ce  = (g & 3) * 8;
            const size_t gA = (size_t)(m0 + row) * HDIM + kc * KT + ce;
            const uint32_t so = (uint32_t)(row * SA + ce) * 2;
            CP_ASYNC16(s0 + so, AHg + gA);
        }
    };

    float acc[2][8][4];
#pragma unroll
    for (int i = 0; i < 2; i++)
#pragma unroll
        for (int j = 0; j < 8; j++)
#pragma unroll
            for (int k = 0; k < 4; k++) acc[i][j][k] = 0.f;

    issue_chunk(0, 0); CP_COMMIT();
    issue_chunk(1, 1); CP_COMMIT();
    issue_chunk(2, 2); CP_COMMIT();

    for (int c = 0; c < NC; c++) {
        // B fragments for this chunk: 8 ldg.128 from L2 (independent of smem)
        uint4 B4[8];
#pragma unroll
        for (int ni = 0; ni < 8; ni++) {
            const int idx = ((nb + ni) * NC + c) * 32 + lane;
            B4[ni] = __ldg(&BF[idx]);
        }

        CP_WAIT2();            // chunk c landed (c+1, c+2 may be pending)
        __syncthreads();       // all warps' cp.async data visible
        if (c + 3 < NC) {      // refill stage (c+3)&3
            issue_chunk(c + 3, (c + 3) & 3);
            CP_COMMIT();
        }

        const uint32_t sAh = sb + (c & 3) * PLANE_BYTES;

#pragma unroll
        for (int kb2 = 0; kb2 < 2; kb2++) {
            const int kcol = kb2 * 16 + ((lane >> 4) << 3);
            // A fragments: 2 m16 subtiles of this warp's 32 rows
            uint32_t a0[4], a1[4];
            {
                const int r0 = warpM * 32 + (lane & 15);
                const int r1 = warpM * 32 + 16 + (lane & 15);
                const uint32_t o0 = (uint32_t)(r0 * SA + kcol) * 2;
                const uint32_t o1 = (uint32_t)(r1 * SA + kcol) * 2;
                LDSM_X4(a0[0], a0[1], a0[2], a0[3], sAh + o0);
                LDSM_X4(a1[0], a1[1], a1[2], a1[3], sAh + o1);
            }
#pragma unroll
            for (int ni = 0; ni < 8; ni++) {
                const uint32_t b0 = kb2 ? B4[ni].z : B4[ni].x;
                const uint32_t b1 = kb2 ? B4[ni].w : B4[ni].y;
                MMA_F16_2(acc[0][ni], a0, b0, b1);
                MMA_F16_2(acc[1][ni], a1, b0, b1);
            }
        }
    }

    // ---- epilogue ----
#pragma unroll
    for (int mi = 0; mi < 2; mi++) {
#pragma unroll
        for (int h = 0; h < 2; h++) {
            const int b = m0 + warpM * 32 + mi * 16 + h * 8 + (lane >> 2);
            float mval = 0.f;
            if (!FIRST) mval = __ldg(&mask[b]);
#pragma unroll
            for (int ni = 0; ni < 8; ni++) {
                const int n = n0 + warpN * 64 + ni * 8 + (lane & 3) * 2;
                const float v0 = acc[mi][ni][2 * h];
                const float v1 = acc[mi][ni][2 * h + 1];
                const float2 si = *reinterpret_cast<const float2*>(
                    &inp[(size_t)b * (3 * HDIM) + n]);
                if (FIRST) {
                    const float2 gi = *reinterpret_cast<const float2*>(
                        &inp[(size_t)b * (3 * HDIM) + 2 * HDIM + n]);
                    const float r0 = si.x / (1.f + __expf(-(v0 + gi.x)));
                    const float r1 = si.y / (1.f + __expf(-(v1 + gi.y)));
                    *reinterpret_cast<uint32_t*>(&g_Rh[(size_t)b * HDIM + n]) =
                        pack_h2(__float2half(r0), __float2half(r1));
                } else {
                    const float2 pv = *reinterpret_cast<const float2*>(
                        &prev[(size_t)b * HDIM + n]);
                    float2 o;
                    o.x = mval * (tanhf(v0 + si.x) + 1.f) + pv.x;
                    o.y = mval * (tanhf(v1 + si.y) + 1.f) + pv.y;
                    *reinterpret_cast<float2*>(&out[(size_t)b * HDIM + n]) = o;
                }
            }
        }
    }
}

// --------------------------------------------------------------------------
extern "C" void kernel_launch(void* const* d_in, const int* in_sizes, int n_in,
                              void* d_out, int out_size) {
    const float* inp  = (const float*)d_in[0];   // (B, 3H)
    const float* prev = (const float*)d_in[1];   // (B, H)
    const float* mask = (const float*)d_in[2];   // (B,)
    const float* Wur  = (const float*)d_in[3];   // (H, 2H)
    const float* U    = (const float*)d_in[4];   // (H, H)
    float* out = (float*)d_out;

    cudaFuncSetAttribute(gemm_kernel<true>,
                         cudaFuncAttributeMaxDynamicSharedMemorySize, SMEM_BYTES);
    cudaFuncSetAttribute(gemm_kernel<false>,
                         cudaFuncAttributeMaxDynamicSharedMemorySize, SMEM_BYTES);

    const int frag_slots = (HDIM / 8) * NC * 32;           // 131072
    wtrans_frag<<<frag_slots / 256, 256>>>(Wur, 2 * HDIM, HDIM, 0);  // Wr
    wtrans_frag<<<frag_slots / 256, 256>>>(U, HDIM, 0, 1);
    psplit_kernel<<<(BATCH * HDIM) / (256 * 4), 256>>>(prev);

    dim3 grid(BATCH / M_TILE, HDIM / N_TILE);
    gemm_kernel<true><<<grid, 256, SMEM_BYTES>>>(inp, prev, mask, out);
    gemm_kernel<false><<<grid, 256, SMEM_BYTES>>>(inp, prev, mask, out);
}

// round 8
// speedup vs baseline: 2.7092x; 1.0459x over previous
#include <cuda_runtime.h>
#include <cuda_fp16.h>
#include <cstdint>

// ============================================================================
// GGRUCell on GB300 — HMMA fp16 single-term GEMMs.
// R8: B fragments also staged through smem via cp.async (4-stage pipeline);
// per-chunk B access is now LDS.128 (29cyc) instead of L2 ldg (~250cyc).
//
//   R   = sigmoid(prev @ Wr + inp[:,2H:]) * inp[:,:H]
//   out = mask * (tanh(R @ U + inp[:,:H]) + 1) + prev   (update gate cancels)
// ============================================================================

#define HDIM   1024
#define BATCH  16384

static constexpr int M_TILE = 128;
static constexpr int N_TILE = 128;
static constexpr int KT     = 32;            // K-chunk
static constexpr int NC     = HDIM / KT;     // 32 chunks
static constexpr int SA     = 40;            // padded smem row stride (fp16)
static constexpr int STAGES = 4;

static constexpr int A_BYTES     = 128 * SA * 2;          // 10240
static constexpr int B_BYTES     = 16 * 512;              // 16 n8-tiles x 512B = 8192
static constexpr int STG_BYTES   = A_BYTES + B_BYTES;     // 18432
static constexpr int OFF_B       = A_BYTES;
static constexpr int SMEM_BYTES  = STAGES * STG_BYTES;    // 73728

// --------------------------------------------------------------------------
__device__ __forceinline__ uint32_t smem_to_u32(const void* p) {
    uint32_t a;
    asm("{ .reg .u64 t; cvta.to.shared.u64 t, %1; cvt.u32.u64 %0, t; }" : "=r"(a) : "l"(p));
    return a;
}
#define CP_ASYNC16(s, g) \
    asm volatile("cp.async.cg.shared.global [%0], [%1], 16;" :: "r"(s), "l"(g) : "memory")
#define CP_COMMIT() asm volatile("cp.async.commit_group;" ::: "memory")
#define CP_WAIT2()  asm volatile("cp.async.wait_group 2;" ::: "memory")

#define LDSM_X4(r0, r1, r2, r3, addr) \
    asm volatile("ldmatrix.sync.aligned.m8n8.x4.shared.b16 {%0,%1,%2,%3}, [%4];" \
                 : "=r"(r0), "=r"(r1), "=r"(r2), "=r"(r3) : "r"(addr))

#define LDS128(v, addr) \
    asm volatile("ld.shared.v4.u32 {%0,%1,%2,%3}, [%4];" \
                 : "=r"((v).x), "=r"((v).y), "=r"((v).z), "=r"((v).w) : "r"(addr))

#define MMA_F16_2(d, a, b0, b1) \
    asm volatile("mma.sync.aligned.m16n8k16.row.col.f32.f16.f16.f32 " \
                 "{%0,%1,%2,%3}, {%4,%5,%6,%7}, {%8,%9}, {%0,%1,%2,%3};" \
                 : "+f"((d)[0]), "+f"((d)[1]), "+f"((d)[2]), "+f"((d)[3]) \
                 : "r"((a)[0]), "r"((a)[1]), "r"((a)[2]), "r"((a)[3]), \
                   "r"(b0), "r"(b1))

// --------------------------------------------------------------------------
// Scratch (no cudaMalloc allowed)
// --------------------------------------------------------------------------
// B fragment-linear planes: index ((n8*NC + k32)*32 + lane) -> uint4 holding
// {b0,b1} for kb2=0 and {b0,b1} for kb2=1 per the m16n8k16 .col B layout.
__device__ uint4 g_W1f[(HDIM / 8) * NC * 32];
__device__ uint4 g_W2f[(HDIM / 8) * NC * 32];
__device__ __half g_Ph[(size_t)BATCH * HDIM];   // prev, fp16
__device__ __half g_Rh[(size_t)BATCH * HDIM];   // R = reset*state, fp16

__device__ __forceinline__ uint32_t pack_h2(__half a, __half b) {
    __half2 t; t.x = a; t.y = b;
    return *reinterpret_cast<uint32_t*>(&t);
}

// --------------------------------------------------------------------------
__global__ void wtrans_frag(const float* __restrict__ W, int ld, int off, int which) {
    const int t    = blockIdx.x * 256 + threadIdx.x;
    const int lane = t & 31;
    const int k32  = (t >> 5) & (NC - 1);
    const int n8   = t >> 10;
    const int n    = n8 * 8 + (lane >> 2);
    const int kb   = k32 * 32 + 2 * (lane & 3);
    uint32_t h[4];
#pragma unroll
    for (int w = 0; w < 4; w++) {
        const int k = kb + 8 * w;
        const float v0 = W[(size_t)k * ld + off + n];
        const float v1 = W[(size_t)(k + 1) * ld + off + n];
        h[w] = pack_h2(__float2half(v0), __float2half(v1));
    }
    uint4* F = which ? g_W2f : g_W1f;
    F[t] = make_uint4(h[0], h[1], h[2], h[3]);
}

// --------------------------------------------------------------------------
__global__ void psplit_kernel(const float* __restrict__ prev) {
    size_t i = ((size_t)blockIdx.x * 256 + threadIdx.x) * 4;
    float4 v = *reinterpret_cast<const float4*>(&prev[i]);
    uint32_t p01 = pack_h2(__float2half(v.x), __float2half(v.y));
    uint32_t p23 = pack_h2(__float2half(v.z), __float2half(v.w));
    *reinterpret_cast<uint2*>(&g_Ph[i]) = make_uint2(p01, p23);
}

// --------------------------------------------------------------------------
// GEMM: CTA 128x128, 8 warps (4M x 2N), warp tile 32x64, K-chunk 32.
// A (LDSM) and B (LDS.128) both staged via 4-deep cp.async pipeline.
// --------------------------------------------------------------------------
template <bool FIRST>
__global__ void __launch_bounds__(256, 2)
gemm_kernel(const float* __restrict__ inp, const float* __restrict__ prev,
            const float* __restrict__ mask, float* __restrict__ out) {
    extern __shared__ char smem_raw[];
    const uint32_t sb = smem_to_u32(smem_raw);

    const int tid   = threadIdx.x;
    const int wid   = tid >> 5;
    const int lane  = tid & 31;
    const int warpM = wid >> 1;       // 4 warps over M (32 rows each)
    const int warpN = wid & 1;        // 2 warps over N (64 cols each)
    const int m0 = blockIdx.x * M_TILE;
    const int n0 = blockIdx.y * N_TILE;

    const __half* AHg = FIRST ? g_Ph : g_Rh;
    const uint4* __restrict__ BF = FIRST ? g_W1f : g_W2f;
    const int nb0 = n0 >> 3;          // CTA's base n8 tile

    auto issue_chunk = [&](int kc, int stage) {
        const uint32_t s0 = sb + stage * STG_BYTES;
        // A: 512 granules of 16B
#pragma unroll
        for (int i = 0; i < 2; i++) {
            const int g   = tid + i * 256;
            const int row = g >> 2;
            const int ce  = (g & 3) * 8;
            const size_t gA = (size_t)(m0 + row) * HDIM + kc * KT + ce;
            const uint32_t so = (uint32_t)(row * SA + ce) * 2;
            CP_ASYNC16(s0 + so, AHg + gA);
        }
        // B: 512 granules of 16B (16 n8-tiles x 32 lanes)
#pragma unroll
        for (int i = 0; i < 2; i++) {
            const int g  = tid + i * 256;
            const int t8 = g >> 5;            // local n8 tile 0..15
            const int ln = g & 31;
            const int idx = ((nb0 + t8) * NC + kc) * 32 + ln;
            CP_ASYNC16(s0 + OFF_B + (uint32_t)g * 16, &BF[idx]);
        }
    };

    float acc[2][8][4];
#pragma unroll
    for (int i = 0; i < 2; i++)
#pragma unroll
        for (int j = 0; j < 8; j++)
#pragma unroll
            for (int k = 0; k < 4; k++) acc[i][j][k] = 0.f;

    issue_chunk(0, 0); CP_COMMIT();
    issue_chunk(1, 1); CP_COMMIT();
    issue_chunk(2, 2); CP_COMMIT();

    for (int c = 0; c < NC; c++) {
        CP_WAIT2();            // chunk c landed
        __syncthreads();
        if (c + 3 < NC) {
            issue_chunk(c + 3, (c + 3) & 3);
            CP_COMMIT();
        }

        const uint32_t s0  = sb + (c & 3) * STG_BYTES;
        const uint32_t sB  = s0 + OFF_B + (uint32_t)warpN * 8 * 512 + lane * 16;

        // B fragments for the chunk: 8 conflict-free LDS.128
        uint4 B4[8];
#pragma unroll
        for (int ni = 0; ni < 8; ni++) LDS128(B4[ni], sB + ni * 512);

#pragma unroll
        for (int kb2 = 0; kb2 < 2; kb2++) {
            const int kcol = kb2 * 16 + ((lane >> 4) << 3);
            uint32_t a0[4], a1[4];
            {
                const int r0 = warpM * 32 + (lane & 15);
                const int r1 = warpM * 32 + 16 + (lane & 15);
                const uint32_t o0 = (uint32_t)(r0 * SA + kcol) * 2;
                const uint32_t o1 = (uint32_t)(r1 * SA + kcol) * 2;
                LDSM_X4(a0[0], a0[1], a0[2], a0[3], s0 + o0);
                LDSM_X4(a1[0], a1[1], a1[2], a1[3], s0 + o1);
            }
#pragma unroll
            for (int ni = 0; ni < 8; ni++) {
                const uint32_t b0 = kb2 ? B4[ni].z : B4[ni].x;
                const uint32_t b1 = kb2 ? B4[ni].w : B4[ni].y;
                MMA_F16_2(acc[0][ni], a0, b0, b1);
                MMA_F16_2(acc[1][ni], a1, b0, b1);
            }
        }
    }

    // ---- epilogue ----
#pragma unroll
    for (int mi = 0; mi < 2; mi++) {
#pragma unroll
        for (int h = 0; h < 2; h++) {
            const int b = m0 + warpM * 32 + mi * 16 + h * 8 + (lane >> 2);
            float mval = 0.f;
            if (!FIRST) mval = __ldg(&mask[b]);
#pragma unroll
            for (int ni = 0; ni < 8; ni++) {
                const int n = n0 + warpN * 64 + ni * 8 + (lane & 3) * 2;
                const float v0 = acc[mi][ni][2 * h];
                const float v1 = acc[mi][ni][2 * h + 1];
                const float2 si = *reinterpret_cast<const float2*>(
                    &inp[(size_t)b * (3 * HDIM) + n]);
                if (FIRST) {
                    const float2 gi = *reinterpret_cast<const float2*>(
                        &inp[(size_t)b * (3 * HDIM) + 2 * HDIM + n]);
                    const float r0 = si.x / (1.f + __expf(-(v0 + gi.x)));
                    const float r1 = si.y / (1.f + __expf(-(v1 + gi.y)));
                    *reinterpret_cast<uint32_t*>(&g_Rh[(size_t)b * HDIM + n]) =
                        pack_h2(__float2half(r0), __float2half(r1));
                } else {
                    const float2 pv = *reinterpret_cast<const float2*>(
                        &prev[(size_t)b * HDIM + n]);
                    float2 o;
                    o.x = mval * (tanhf(v0 + si.x) + 1.f) + pv.x;
                    o.y = mval * (tanhf(v1 + si.y) + 1.f) + pv.y;
                    *reinterpret_cast<float2*>(&out[(size_t)b * HDIM + n]) = o;
                }
            }
        }
    }
}

// --------------------------------------------------------------------------
extern "C" void kernel_launch(void* const* d_in, const int* in_sizes, int n_in,
                              void* d_out, int out_size) {
    const float* inp  = (const float*)d_in[0];   // (B, 3H)
    const float* prev = (const float*)d_in[1];   // (B, H)
    const float* mask = (const float*)d_in[2];   // (B,)
    const float* Wur  = (const float*)d_in[3];   // (H, 2H)
    const float* U    = (const float*)d_in[4];   // (H, H)
    float* out = (float*)d_out;

    cudaFuncSetAttribute(gemm_kernel<true>,
                         cudaFuncAttributeMaxDynamicSharedMemorySize, SMEM_BYTES);
    cudaFuncSetAttribute(gemm_kernel<false>,
                         cudaFuncAttributeMaxDynamicSharedMemorySize, SMEM_BYTES);

    const int frag_slots = (HDIM / 8) * NC * 32;           // 131072
    wtrans_frag<<<frag_slots / 256, 256>>>(Wur, 2 * HDIM, HDIM, 0);  // Wr
    wtrans_frag<<<frag_slots / 256, 256>>>(U, HDIM, 0, 1);
    psplit_kernel<<<(BATCH * HDIM) / (256 * 4), 256>>>(prev);

    dim3 grid(BATCH / M_TILE, HDIM / N_TILE);
    gemm_kernel<true><<<grid, 256, SMEM_BYTES>>>(inp, prev, mask, out);
    gemm_kernel<false><<<grid, 256, SMEM_BYTES>>>(inp, prev, mask, out);
}

// round 9
// speedup vs baseline: 2.7861x; 1.0284x over previous
#include <cuda_runtime.h>
#include <cuda_fp16.h>
#include <cstdint>

// ============================================================================
// GGRUCell on GB300 — HMMA fp16 single-term GEMMs.
// R9: K-chunk 64 (16 iterations, was 32) + 3-stage cp.async pipeline.
// Halves per-iteration serialization (barrier, pipeline refill, frag ramp).
//
//   R   = sigmoid(prev @ Wr + inp[:,2H:]) * inp[:,:H]
//   out = mask * (tanh(R @ U + inp[:,:H]) + 1) + prev   (update gate cancels)
// ============================================================================

#define HDIM   1024
#define BATCH  16384

static constexpr int M_TILE = 128;
static constexpr int N_TILE = 128;
static constexpr int KT     = 64;            // K-chunk (elems)
static constexpr int NC2    = HDIM / KT;     // 16 chunks
static constexpr int NC     = HDIM / 32;     // 32 k32-granules (B frag layout)
static constexpr int SA     = 72;            // padded smem row stride (fp16)
static constexpr int STAGES = 3;

static constexpr int A_BYTES     = 128 * SA * 2;          // 18432
static constexpr int B_BYTES     = 16 * 2 * 512;          // 16 n8-tiles x 2 ksub x 512B
static constexpr int STG_BYTES   = A_BYTES + B_BYTES;     // 34816
static constexpr int OFF_B       = A_BYTES;
static constexpr int SMEM_BYTES  = STAGES * STG_BYTES;    // 104448

// --------------------------------------------------------------------------
__device__ __forceinline__ uint32_t smem_to_u32(const void* p) {
    uint32_t a;
    asm("{ .reg .u64 t; cvta.to.shared.u64 t, %1; cvt.u32.u64 %0, t; }" : "=r"(a) : "l"(p));
    return a;
}
#define CP_ASYNC16(s, g) \
    asm volatile("cp.async.cg.shared.global [%0], [%1], 16;" :: "r"(s), "l"(g) : "memory")
#define CP_COMMIT() asm volatile("cp.async.commit_group;" ::: "memory")
#define CP_WAIT1()  asm volatile("cp.async.wait_group 1;" ::: "memory")
#define CP_WAIT0()  asm volatile("cp.async.wait_group 0;" ::: "memory")

#define LDSM_X4(r0, r1, r2, r3, addr) \
    asm volatile("ldmatrix.sync.aligned.m8n8.x4.shared.b16 {%0,%1,%2,%3}, [%4];" \
                 : "=r"(r0), "=r"(r1), "=r"(r2), "=r"(r3) : "r"(addr))

#define LDS128(v, addr) \
    asm volatile("ld.shared.v4.u32 {%0,%1,%2,%3}, [%4];" \
                 : "=r"((v).x), "=r"((v).y), "=r"((v).z), "=r"((v).w) : "r"(addr))

#define MMA_F16_2(d, a, b0, b1) \
    asm volatile("mma.sync.aligned.m16n8k16.row.col.f32.f16.f16.f32 " \
                 "{%0,%1,%2,%3}, {%4,%5,%6,%7}, {%8,%9}, {%0,%1,%2,%3};" \
                 : "+f"((d)[0]), "+f"((d)[1]), "+f"((d)[2]), "+f"((d)[3]) \
                 : "r"((a)[0]), "r"((a)[1]), "r"((a)[2]), "r"((a)[3]), \
                   "r"(b0), "r"(b1))

// --------------------------------------------------------------------------
// Scratch (no cudaMalloc allowed)
// --------------------------------------------------------------------------
// B fragment-linear planes: index ((n8*NC + k32)*32 + lane) -> uint4 holding
// {b0,b1} for first k16 and {b0,b1} for second k16 of that k32 granule,
// per the m16n8k16 .col B layout (thread t: n=t/4, k=2*(t%4)+{0,1},+8,..).
__device__ uint4 g_W1f[(HDIM / 8) * NC * 32];
__device__ uint4 g_W2f[(HDIM / 8) * NC * 32];
__device__ __half g_Ph[(size_t)BATCH * HDIM];   // prev, fp16
__device__ __half g_Rh[(size_t)BATCH * HDIM];   // R = reset*state, fp16

__device__ __forceinline__ uint32_t pack_h2(__half a, __half b) {
    __half2 t; t.x = a; t.y = b;
    return *reinterpret_cast<uint32_t*>(&t);
}

// --------------------------------------------------------------------------
__global__ void wtrans_frag(const float* __restrict__ W, int ld, int off, int which) {
    const int t    = blockIdx.x * 256 + threadIdx.x;
    const int lane = t & 31;
    const int k32  = (t >> 5) & (NC - 1);
    const int n8   = t >> 10;
    const int n    = n8 * 8 + (lane >> 2);
    const int kb   = k32 * 32 + 2 * (lane & 3);
    uint32_t h[4];
#pragma unroll
    for (int w = 0; w < 4; w++) {
        const int k = kb + 8 * w;
        const float v0 = W[(size_t)k * ld + off + n];
        const float v1 = W[(size_t)(k + 1) * ld + off + n];
        h[w] = pack_h2(__float2half(v0), __float2half(v1));
    }
    uint4* F = which ? g_W2f : g_W1f;
    F[t] = make_uint4(h[0], h[1], h[2], h[3]);
}

// --------------------------------------------------------------------------
__global__ void psplit_kernel(const float* __restrict__ prev) {
    size_t i = ((size_t)blockIdx.x * 256 + threadIdx.x) * 4;
    float4 v = *reinterpret_cast<const float4*>(&prev[i]);
    uint32_t p01 = pack_h2(__float2half(v.x), __float2half(v.y));
    uint32_t p23 = pack_h2(__float2half(v.z), __float2half(v.w));
    *reinterpret_cast<uint2*>(&g_Ph[i]) = make_uint2(p01, p23);
}

// --------------------------------------------------------------------------
// GEMM: CTA 128x128, 8 warps (4M x 2N), warp tile 32x64, K-chunk 64,
// 3-stage cp.async pipeline, 16 iterations.
// --------------------------------------------------------------------------
template <bool FIRST>
__global__ void __launch_bounds__(256, 2)
gemm_kernel(const float* __restrict__ inp, const float* __restrict__ prev,
            const float* __restrict__ mask, float* __restrict__ out) {
    extern __shared__ char smem_raw[];
    const uint32_t sb = smem_to_u32(smem_raw);

    const int tid   = threadIdx.x;
    const int wid   = tid >> 5;
    const int lane  = tid & 31;
    const int warpM = wid >> 1;       // 4 warps over M (32 rows each)
    const int warpN = wid & 1;        // 2 warps over N (64 cols each)
    const int m0 = blockIdx.x * M_TILE;
    const int n0 = blockIdx.y * N_TILE;

    const __half* AHg = FIRST ? g_Ph : g_Rh;
    const uint4* __restrict__ BF = FIRST ? g_W1f : g_W2f;
    const int nb0 = n0 >> 3;          // CTA's base n8 tile

    auto issue_chunk = [&](int kc, int stage) {
        const uint32_t s0 = sb + stage * STG_BYTES;
        // A: 128 rows x 8 granules (16B) = 1024 granules, 4/thread.
        // threads 0-7 cover row 0 contiguously (perfect coalescing).
#pragma unroll
        for (int i = 0; i < 4; i++) {
            const int g   = tid + i * 256;
            const int row = g >> 3;
            const int ce  = (g & 7) * 8;
            const size_t gA = (size_t)(m0 + row) * HDIM + kc * KT + ce;
            const uint32_t so = (uint32_t)(row * SA + ce) * 2;
            CP_ASYNC16(s0 + so, AHg + gA);
        }
        // B: 16 tiles x 2 ksub x 32 lanes = 1024 granules, 4/thread.
#pragma unroll
        for (int i = 0; i < 4; i++) {
            const int g    = tid + i * 256;
            const int t8   = g >> 6;
            const int ksub = (g >> 5) & 1;
            const int ln   = g & 31;
            const int idx  = ((nb0 + t8) * NC + 2 * kc + ksub) * 32 + ln;
            CP_ASYNC16(s0 + OFF_B + (uint32_t)g * 16, &BF[idx]);
        }
    };

    float acc[2][8][4];
#pragma unroll
    for (int i = 0; i < 2; i++)
#pragma unroll
        for (int j = 0; j < 8; j++)
#pragma unroll
            for (int k = 0; k < 4; k++) acc[i][j][k] = 0.f;

    issue_chunk(0, 0); CP_COMMIT();
    issue_chunk(1, 1); CP_COMMIT();

    for (int c = 0; c < NC2; c++) {
        if (c == NC2 - 1) { CP_WAIT0(); } else { CP_WAIT1(); }
        __syncthreads();
        if (c + 2 < NC2) {
            issue_chunk(c + 2, (c + 2) % STAGES);
            CP_COMMIT();
        }

        const uint32_t s0 = sb + (c % STAGES) * STG_BYTES;
        const uint32_t sBbase = s0 + OFF_B + (uint32_t)warpN * 8 * 1024 + lane * 16;

#pragma unroll
        for (int ksub = 0; ksub < 2; ksub++) {
            // B fragments for this k32: 8 conflict-free LDS.128
            uint4 B4[8];
#pragma unroll
            for (int ni = 0; ni < 8; ni++)
                LDS128(B4[ni], sBbase + (uint32_t)(ni * 2 + ksub) * 512);

#pragma unroll
            for (int kb2 = 0; kb2 < 2; kb2++) {
                const int kcol = ksub * 32 + kb2 * 16 + ((lane >> 4) << 3);
                uint32_t a0[4], a1[4];
                {
                    const int r0 = warpM * 32 + (lane & 15);
                    const int r1 = warpM * 32 + 16 + (lane & 15);
                    const uint32_t o0 = (uint32_t)(r0 * SA + kcol) * 2;
                    const uint32_t o1 = (uint32_t)(r1 * SA + kcol) * 2;
                    LDSM_X4(a0[0], a0[1], a0[2], a0[3], s0 + o0);
                    LDSM_X4(a1[0], a1[1], a1[2], a1[3], s0 + o1);
                }
#pragma unroll
                for (int ni = 0; ni < 8; ni++) {
                    const uint32_t b0 = kb2 ? B4[ni].z : B4[ni].x;
                    const uint32_t b1 = kb2 ? B4[ni].w : B4[ni].y;
                    MMA_F16_2(acc[0][ni], a0, b0, b1);
                    MMA_F16_2(acc[1][ni], a1, b0, b1);
                }
            }
        }
    }

    // ---- epilogue ----
#pragma unroll
    for (int mi = 0; mi < 2; mi++) {
#pragma unroll
        for (int h = 0; h < 2; h++) {
            const int b = m0 + warpM * 32 + mi * 16 + h * 8 + (lane >> 2);
            float mval = 0.f;
            if (!FIRST) mval = __ldg(&mask[b]);
#pragma unroll
            for (int ni = 0; ni < 8; ni++) {
                const int n = n0 + warpN * 64 + ni * 8 + (lane & 3) * 2;
                const float v0 = acc[mi][ni][2 * h];
                const float v1 = acc[mi][ni][2 * h + 1];
                const float2 si = *reinterpret_cast<const float2*>(
                    &inp[(size_t)b * (3 * HDIM) + n]);
                if (FIRST) {
                    const float2 gi = *reinterpret_cast<const float2*>(
                        &inp[(size_t)b * (3 * HDIM) + 2 * HDIM + n]);
                    const float r0 = si.x / (1.f + __expf(-(v0 + gi.x)));
                    const float r1 = si.y / (1.f + __expf(-(v1 + gi.y)));
                    *reinterpret_cast<uint32_t*>(&g_Rh[(size_t)b * HDIM + n]) =
                        pack_h2(__float2half(r0), __float2half(r1));
                } else {
                    const float2 pv = *reinterpret_cast<const float2*>(
                        &prev[(size_t)b * HDIM + n]);
                    float2 o;
                    o.x = mval * (tanhf(v0 + si.x) + 1.f) + pv.x;
                    o.y = mval * (tanhf(v1 + si.y) + 1.f) + pv.y;
                    *reinterpret_cast<float2*>(&out[(size_t)b * HDIM + n]) = o;
                }
            }
        }
    }
}

// --------------------------------------------------------------------------
extern "C" void kernel_launch(void* const* d_in, const int* in_sizes, int n_in,
                              void* d_out, int out_size) {
    const float* inp  = (const float*)d_in[0];   // (B, 3H)
    const float* prev = (const float*)d_in[1];   // (B, H)
    const float* mask = (const float*)d_in[2];   // (B,)
    const float* Wur  = (const float*)d_in[3];   // (H, 2H)
    const float* U    = (const float*)d_in[4];   // (H, H)
    float* out = (float*)d_out;

    cudaFuncSetAttribute(gemm_kernel<true>,
                         cudaFuncAttributeMaxDynamicSharedMemorySize, SMEM_BYTES);
    cudaFuncSetAttribute(gemm_kernel<false>,
                         cudaFuncAttributeMaxDynamicSharedMemorySize, SMEM_BYTES);

    const int frag_slots = (HDIM / 8) * NC * 32;           // 131072
    wtrans_frag<<<frag_slots / 256, 256>>>(Wur, 2 * HDIM, HDIM, 0);  // Wr
    wtrans_frag<<<frag_slots / 256, 256>>>(U, HDIM, 0, 1);
    psplit_kernel<<<(BATCH * HDIM) / (256 * 4), 256>>>(prev);

    dim3 grid(BATCH / M_TILE, HDIM / N_TILE);
    gemm_kernel<true><<<grid, 256, SMEM_BYTES>>>(inp, prev, mask, out);
    gemm_kernel<false><<<grid, 256, SMEM_BYTES>>>(inp, prev, mask, out);
}